// round 2
// baseline (speedup 1.0000x reference)
#include <cuda_runtime.h>
#include <cstdint>
#include <math.h>

#define B_    2
#define N_    65536
#define K_    4
#define HID_  64
#define C_    128

typedef unsigned long long u64;

// Scratch (static device globals; no runtime allocation)
__device__ float g_hx [(size_t)B_ * N_ * C_];    // [b][n][c]  c<64: h, c>=64: x
__device__ float g_rhx[(size_t)B_ * N_ * C_];    // [b][n][c]  c<64: r*h, c>=64: x
__device__ float g_z  [(size_t)B_ * N_ * HID_];  // [b][n][o]  sigmoid(z)
__device__ float g_wT [3 * C_ * HID_];           // [gate][c][o]  transposed w_out

__device__ __forceinline__ u64 pk2(float a, float b) {
    u64 r; asm("mov.b64 %0, {%1,%2};" : "=l"(r) : "f"(a), "f"(b)); return r;
}
__device__ __forceinline__ void up2(u64 v, float& a, float& b) {
    asm("mov.b64 {%0,%1}, %2;" : "=f"(a), "=f"(b) : "l"(v));
}
__device__ __forceinline__ void fma2(u64& d, u64 a, u64 b) {
    asm("fma.rn.f32x2 %0, %1, %2, %0;" : "+l"(d) : "l"(a), "l"(b));
}
__device__ __forceinline__ float sigm(float v) { return 1.0f / (1.0f + __expf(-v)); }

// ---------------------------------------------------------------------------
// Transpose w_out -> g_wT[g][c][o]
// ---------------------------------------------------------------------------
__global__ void k_wT(const float* __restrict__ wz, const float* __restrict__ wr,
                     const float* __restrict__ wq) {
    int i = blockIdx.x * blockDim.x + threadIdx.x;
    if (i >= 3 * C_ * HID_) return;
    int g = i / (C_ * HID_);
    int r = i - g * (C_ * HID_);
    int c = r / HID_;
    int o = r - c * HID_;
    const float* w = (g == 0) ? wz : ((g == 1) ? wr : wq);
    g_wT[i] = w[o * C_ + c];
}

// ---------------------------------------------------------------------------
// Build hx_t[b][n][c] = (c<64 ? h[b][c][n] : x[b][c-64][n])
// ---------------------------------------------------------------------------
__global__ __launch_bounds__(256) void k_tr(const float* __restrict__ h,
                                            const float* __restrict__ x) {
    __shared__ float t[C_][33];
    const int b  = blockIdx.x >> 11;            // N_/32 = 2048 blocks per batch
    const int n0 = (blockIdx.x & 2047) * 32;
    const int tid  = threadIdx.x;
    const int lane = tid & 31;
    const int w    = tid >> 5;

    for (int r = w; r < C_; r += 8) {
        const float* src = (r < HID_)
            ? (h + ((size_t)(b * HID_ + r)) * N_)
            : (x + ((size_t)(b * HID_ + (r - HID_))) * N_);
        t[r][lane] = src[n0 + lane];
    }
    __syncthreads();

    const int nn = tid >> 3;
    const int q0 = tid & 7;
    float* dst = g_hx + ((size_t)(b * N_ + n0 + nn)) * C_;
#pragma unroll
    for (int k = 0; k < 4; k++) {
        int c = 4 * (q0 + 8 * k);
        float4 v = make_float4(t[c][nn], t[c + 1][nn], t[c + 2][nn], t[c + 3][nn]);
        *(float4*)(dst + c) = v;
    }
}

// ---------------------------------------------------------------------------
// ZR kernel: per block of 32 points, compute z and r gates.
// Phase 1: coalesced neighbor gather of hx rows, depthwise agg -> smem
// Phase 2: 64x128 matvec via packed f32x2 FMA; writes sigmoid(z) and r*h
// Also copies the x half into g_rhx.
// ---------------------------------------------------------------------------
__global__ __launch_bounds__(256, 3) void k_zr(
    const float* __restrict__ xyz, const int* __restrict__ knn,
    const float* __restrict__ wzp, const float* __restrict__ bzp,
    const float* __restrict__ bzo,
    const float* __restrict__ wrp, const float* __restrict__ brp,
    const float* __restrict__ bro) {
    __shared__ __align__(16) float agg[2][C_][36];
    __shared__ float srel[32][12];
    __shared__ int   sidx[32][4];

    const int b   = blockIdx.x >> 11;
    const int n0  = (blockIdx.x & 2047) * 32;
    const int tid = threadIdx.x;

    // Copy x half into g_rhx (independent of everything else)
    {
        const float* src = g_hx  + ((size_t)b * N_ + n0) * C_ + HID_;
        float*       dst = g_rhx + ((size_t)b * N_ + n0) * C_ + HID_;
        for (int i = tid; i < 32 * 32; i += 256) {
            int pt = i >> 5, k2 = i & 31;
            *(float2*)(dst + (size_t)pt * C_ + 2 * k2) =
                *(const float2*)(src + (size_t)pt * C_ + 2 * k2);
        }
    }

    // Stage neighbor indices + relative positions
    if (tid < 128) {
        int pt = tid >> 2, j = tid & 3;
        int n  = n0 + pt;
        int m  = knn[((size_t)b * N_ + n) * K_ + j];
        sidx[pt][j] = m;
        const float* xb = xyz + (size_t)b * 3 * N_;
#pragma unroll
        for (int d = 0; d < 3; d++)
            srel[pt][j * 3 + d] = xb[(size_t)d * N_ + m] - xb[(size_t)d * N_ + n];
    }
    __syncthreads();

    const int lane = tid & 31;
    const int w    = tid >> 5;

    // Phase 1: gather + depthwise agg (lane owns channels 4*lane..4*lane+3)
    {
        float wp[2][4][3], bp[2][4];
#pragma unroll
        for (int i = 0; i < 4; i++) {
            int c = 4 * lane + i;
#pragma unroll
            for (int d = 0; d < 3; d++) {
                wp[0][i][d] = wzp[c * 3 + d];
                wp[1][i][d] = wrp[c * 3 + d];
            }
            bp[0][i] = bzp[c];
            bp[1][i] = brp[c];
        }
        const float* hxb = g_hx + (size_t)b * N_ * C_;
#pragma unroll
        for (int u = 0; u < 4; u++) {
            int pt = w + 8 * u;
            float az[4] = {0.f, 0.f, 0.f, 0.f};
            float ar[4] = {0.f, 0.f, 0.f, 0.f};
#pragma unroll
            for (int j = 0; j < 4; j++) {
                int m = sidx[pt][j];
                float4 gv = *(const float4*)(hxb + (size_t)m * C_ + 4 * lane);
                float r0 = srel[pt][3 * j + 0];
                float r1 = srel[pt][3 * j + 1];
                float r2 = srel[pt][3 * j + 2];
                float gg[4] = {gv.x, gv.y, gv.z, gv.w};
#pragma unroll
                for (int i = 0; i < 4; i++) {
                    float wz = fmaf(wp[0][i][0], r0,
                                fmaf(wp[0][i][1], r1,
                                fmaf(wp[0][i][2], r2, bp[0][i])));
                    az[i] = fmaf(wz, gg[i], az[i]);
                    float wr_ = fmaf(wp[1][i][0], r0,
                                 fmaf(wp[1][i][1], r1,
                                 fmaf(wp[1][i][2], r2, bp[1][i])));
                    ar[i] = fmaf(wr_, gg[i], ar[i]);
                }
            }
#pragma unroll
            for (int i = 0; i < 4; i++) {
                agg[0][4 * lane + i][pt] = az[i];
                agg[1][4 * lane + i][pt] = ar[i];
            }
        }
    }
    __syncthreads();

    // Phase 2: matvec. warps 0-3 -> z gate, warps 4-7 -> r gate.
    // thread: outputs {o0, o0+32}, points p0..p0+7 as 4 packed pairs.
    {
        const int o0 = tid & 31;
        const int pg = (tid >> 5) & 3;
        const int g  = tid >> 7;
        const int p0 = pg * 8;
        const float* wt = g_wT + g * C_ * HID_;
        const float* bo = g ? bro : bzo;

        u64 acc[4][2];
        {
            float bb0 = bo[o0], bb1 = bo[o0 + 32];
#pragma unroll
            for (int k = 0; k < 4; k++) {
                acc[k][0] = pk2(bb0, bb0);
                acc[k][1] = pk2(bb1, bb1);
            }
        }
#pragma unroll 2
        for (int c = 0; c < C_; c++) {
            float4 aA = *(const float4*)&agg[g][c][p0];
            float4 aB = *(const float4*)&agg[g][c][p0 + 4];
            float w0 = wt[c * HID_ + o0];
            float w1 = wt[c * HID_ + o0 + 32];
            u64 W0 = pk2(w0, w0), W1 = pk2(w1, w1);
            u64 A0 = pk2(aA.x, aA.y), A1 = pk2(aA.z, aA.w);
            u64 A2 = pk2(aB.x, aB.y), A3 = pk2(aB.z, aB.w);
            fma2(acc[0][0], A0, W0); fma2(acc[0][1], A0, W1);
            fma2(acc[1][0], A1, W0); fma2(acc[1][1], A1, W1);
            fma2(acc[2][0], A2, W0); fma2(acc[2][1], A2, W1);
            fma2(acc[3][0], A3, W0); fma2(acc[3][1], A3, W1);
        }
#pragma unroll
        for (int k = 0; k < 4; k++) {
            float e0, e1, f0, f1;
            up2(acc[k][0], e0, e1);
            up2(acc[k][1], f0, f1);
            size_t baseA = (size_t)b * N_ + (n0 + p0 + 2 * k);
            size_t baseB = baseA + 1;
            if (g == 0) {
                g_z[baseA * HID_ + o0]      = sigm(e0);
                g_z[baseB * HID_ + o0]      = sigm(e1);
                g_z[baseA * HID_ + o0 + 32] = sigm(f0);
                g_z[baseB * HID_ + o0 + 32] = sigm(f1);
            } else {
                float hA0 = g_hx[baseA * C_ + o0];
                float hB0 = g_hx[baseB * C_ + o0];
                float hA1 = g_hx[baseA * C_ + o0 + 32];
                float hB1 = g_hx[baseB * C_ + o0 + 32];
                g_rhx[baseA * C_ + o0]      = sigm(e0) * hA0;
                g_rhx[baseB * C_ + o0]      = sigm(e1) * hB0;
                g_rhx[baseA * C_ + o0 + 32] = sigm(f0) * hA1;
                g_rhx[baseB * C_ + o0 + 32] = sigm(f1) * hB1;
            }
        }
    }
}

// ---------------------------------------------------------------------------
// Q kernel: gather r*h||x, q gate, GRU combine, coalesced output write.
// ---------------------------------------------------------------------------
__global__ __launch_bounds__(256, 3) void k_q(
    const float* __restrict__ xyz, const int* __restrict__ knn,
    const float* __restrict__ wqp, const float* __restrict__ bqp,
    const float* __restrict__ bqo, float* __restrict__ out) {
    __shared__ __align__(16) float agg[C_][36];
    __shared__ float osm[HID_][33];
    __shared__ float srel[32][12];
    __shared__ int   sidx[32][4];

    const int b   = blockIdx.x >> 11;
    const int n0  = (blockIdx.x & 2047) * 32;
    const int tid = threadIdx.x;

    if (tid < 128) {
        int pt = tid >> 2, j = tid & 3;
        int n  = n0 + pt;
        int m  = knn[((size_t)b * N_ + n) * K_ + j];
        sidx[pt][j] = m;
        const float* xb = xyz + (size_t)b * 3 * N_;
#pragma unroll
        for (int d = 0; d < 3; d++)
            srel[pt][j * 3 + d] = xb[(size_t)d * N_ + m] - xb[(size_t)d * N_ + n];
    }
    __syncthreads();

    const int lane = tid & 31;
    const int w    = tid >> 5;

    // Phase 1
    {
        float wp[4][3], bp[4];
#pragma unroll
        for (int i = 0; i < 4; i++) {
            int c = 4 * lane + i;
#pragma unroll
            for (int d = 0; d < 3; d++) wp[i][d] = wqp[c * 3 + d];
            bp[i] = bqp[c];
        }
        const float* fb = g_rhx + (size_t)b * N_ * C_;
#pragma unroll
        for (int u = 0; u < 4; u++) {
            int pt = w + 8 * u;
            float a[4] = {0.f, 0.f, 0.f, 0.f};
#pragma unroll
            for (int j = 0; j < 4; j++) {
                int m = sidx[pt][j];
                float4 gv = *(const float4*)(fb + (size_t)m * C_ + 4 * lane);
                float r0 = srel[pt][3 * j + 0];
                float r1 = srel[pt][3 * j + 1];
                float r2 = srel[pt][3 * j + 2];
                float gg[4] = {gv.x, gv.y, gv.z, gv.w};
#pragma unroll
                for (int i = 0; i < 4; i++) {
                    float wv = fmaf(wp[i][0], r0,
                               fmaf(wp[i][1], r1,
                               fmaf(wp[i][2], r2, bp[i])));
                    a[i] = fmaf(wv, gg[i], a[i]);
                }
            }
#pragma unroll
            for (int i = 0; i < 4; i++) agg[4 * lane + i][pt] = a[i];
        }
    }
    __syncthreads();

    // Phase 2: matvec + tanh + GRU combine into osm[o][p]
    {
        const int o0 = tid & 31;
        const int pg = tid >> 5;      // 0..7
        const int p0 = pg * 4;
        const float* wt = g_wT + 2 * C_ * HID_;

        u64 acc[2][2];
        {
            float bb0 = bqo[o0], bb1 = bqo[o0 + 32];
            acc[0][0] = pk2(bb0, bb0); acc[0][1] = pk2(bb1, bb1);
            acc[1][0] = pk2(bb0, bb0); acc[1][1] = pk2(bb1, bb1);
        }
#pragma unroll 2
        for (int c = 0; c < C_; c++) {
            float4 aA = *(const float4*)&agg[c][p0];
            float w0 = wt[c * HID_ + o0];
            float w1 = wt[c * HID_ + o0 + 32];
            u64 W0 = pk2(w0, w0), W1 = pk2(w1, w1);
            u64 A0 = pk2(aA.x, aA.y), A1 = pk2(aA.z, aA.w);
            fma2(acc[0][0], A0, W0); fma2(acc[0][1], A0, W1);
            fma2(acc[1][0], A1, W0); fma2(acc[1][1], A1, W1);
        }
#pragma unroll
        for (int k = 0; k < 2; k++) {
            float v[4];
            up2(acc[k][0], v[0], v[1]);   // (p0+2k, o0), (p0+2k+1, o0)
            up2(acc[k][1], v[2], v[3]);   // (p0+2k, o0+32), (p0+2k+1, o0+32)
#pragma unroll
            for (int s = 0; s < 4; s++) {
                int p = p0 + 2 * k + (s & 1);
                int o = o0 + 32 * (s >> 1);
                size_t base = (size_t)b * N_ + (n0 + p);
                float z  = g_z[base * HID_ + o];
                float hh = g_hx[base * C_ + o];
                float qv = tanhf(v[s]);
                osm[o][p] = (1.0f - z) * hh + z * qv;
            }
        }
    }
    __syncthreads();

    // Phase 3: coalesced output  out[b][o][n0..n0+31]
    // 8 warps x 8 rows = all 64 output channels (was 2 rows/warp: the R1 bug)
#pragma unroll
    for (int r = 0; r < 8; r++) {
        int o = 8 * w + r;
        out[((size_t)b * HID_ + o) * N_ + n0 + lane] = osm[o][lane];
    }
}

// ---------------------------------------------------------------------------
extern "C" void kernel_launch(void* const* d_in, const int* in_sizes, int n_in,
                              void* d_out, int out_size) {
    const float* xyz = (const float*)d_in[0];
    const float* h   = (const float*)d_in[1];
    const float* x   = (const float*)d_in[2];
    const int*   knn = (const int*)  d_in[3];
    const float* wzp = (const float*)d_in[4];
    const float* bzp = (const float*)d_in[5];
    const float* wzo = (const float*)d_in[6];
    const float* bzo = (const float*)d_in[7];
    const float* wrp = (const float*)d_in[8];
    const float* brp = (const float*)d_in[9];
    const float* wro = (const float*)d_in[10];
    const float* bro = (const float*)d_in[11];
    const float* wqp = (const float*)d_in[12];
    const float* bqp = (const float*)d_in[13];
    const float* wqo = (const float*)d_in[14];
    const float* bqo = (const float*)d_in[15];
    float* out = (float*)d_out;

    const int nblk = (B_ * N_) / 32;   // 4096
    k_wT<<<(3 * C_ * HID_ + 255) / 256, 256>>>(wzo, wro, wqo);
    k_tr<<<nblk, 256>>>(h, x);
    k_zr<<<nblk, 256>>>(xyz, knn, wzp, bzp, bzo, wrp, brp, bro);
    k_q <<<nblk, 256>>>(xyz, knn, wqp, bqp, bqo, out);
}